// round 13
// baseline (speedup 1.0000x reference)
#include <cuda_runtime.h>
#include <math.h>

// ---------------------------------------------------------------------------
// Problem constants: B=4, S=4096, D=512, CHUNK=64  ->  T = B*S = 16384 tokens
// ---------------------------------------------------------------------------
#define T_TOK   16384
#define DIM     512
#define CHUNK   64
#define NCHUNKS (T_TOK / CHUNK)      // 256
#define CTXW    (4 * DIM)            // 2048
#define HIDW    (2 * DIM)            // 1024
#define LN_EPS  1e-5f

// ---------------------------------------------------------------------------
// Scratch (allocation-free rule: __device__ globals)
// ---------------------------------------------------------------------------
__device__ float g_omega[(size_t)T_TOK * DIM];    //  33.5 MB
__device__ float g_ctx  [(size_t)T_TOK * CTXW];   // 134.2 MB (ctx, LN'd in place)
__device__ float g_h    [(size_t)T_TOK * HIDW];   //  67.1 MB (post-GELU hidden)

// ---------------------------------------------------------------------------
// SGEMM: C[M,N] = A[M,K] @ B[K,N] + bias, with epilogue variants.
// BM=BN=128, BK=16, 256 threads, 8x8 per-thread micro-tile.
// All M,N,K here are multiples of the tile sizes -> no bounds checks.
// EPI: 0 = bias only, 1 = bias + exact GELU (erf), 2 = bias + residual add
// ---------------------------------------------------------------------------
#define BM 128
#define BN 128
#define BK 16
#define TM 8
#define TN 8

__device__ __forceinline__ float gelu_exact(float v) {
    return 0.5f * v * (1.0f + erff(v * 0.70710678118654752440f));
}

template <int EPI>
__global__ void __launch_bounds__(256)
sgemm_kernel(const float* __restrict__ A, const float* __restrict__ B,
             const float* __restrict__ bias, const float* __restrict__ R,
             float* __restrict__ C, int M, int N, int K)
{
    __shared__ float As[BK][BM];   // A tile, transposed (k-major)
    __shared__ float Bs[BK][BN];

    const int tid = threadIdx.x;
    const int tx  = tid & 15;       // 0..15 -> col group
    const int ty  = tid >> 4;       // 0..15 -> row group
    const int rowBase = blockIdx.y * BM;
    const int colBase = blockIdx.x * BN;

    const float* Ab = A + (size_t)rowBase * K;
    const float* Bb = B + colBase;

    float acc[TM][TN];
#pragma unroll
    for (int i = 0; i < TM; i++)
#pragma unroll
        for (int j = 0; j < TN; j++) acc[i][j] = 0.0f;

    for (int k0 = 0; k0 < K; k0 += BK) {
        // ---- load A tile: 128 rows x 16 cols = 512 float4, 2 per thread ----
#pragma unroll
        for (int i = 0; i < 2; i++) {
            int id = i * 256 + tid;          // 0..511
            int r  = id >> 2;                // 0..127 (tile row)
            int kq = (id & 3) << 2;          // 0,4,8,12 (k offset)
            float4 v = *(const float4*)(Ab + (size_t)r * K + k0 + kq);
            As[kq + 0][r] = v.x;
            As[kq + 1][r] = v.y;
            As[kq + 2][r] = v.z;
            As[kq + 3][r] = v.w;
        }
        // ---- load B tile: 16 rows x 128 cols = 512 float4, 2 per thread ----
#pragma unroll
        for (int i = 0; i < 2; i++) {
            int id = i * 256 + tid;          // 0..511
            int kr = id >> 5;                // 0..15
            int cq = (id & 31) << 2;         // 0..124
            *(float4*)&Bs[kr][cq] =
                *(const float4*)(Bb + (size_t)(k0 + kr) * N + cq);
        }
        __syncthreads();

#pragma unroll
        for (int kk = 0; kk < BK; kk++) {
            float ra[TM], rb[TN];
#pragma unroll
            for (int i = 0; i < TM; i++) ra[i] = As[kk][ty * TM + i];
#pragma unroll
            for (int j = 0; j < TN; j++) rb[j] = Bs[kk][tx * TN + j];
#pragma unroll
            for (int i = 0; i < TM; i++)
#pragma unroll
                for (int j = 0; j < TN; j++)
                    acc[i][j] = fmaf(ra[i], rb[j], acc[i][j]);
        }
        __syncthreads();
    }

    // ---- epilogue ----
#pragma unroll
    for (int i = 0; i < TM; i++) {
        int row = rowBase + ty * TM + i;
#pragma unroll
        for (int j = 0; j < TN; j += 4) {
            int col = colBase + tx * TN + j;
            float4 bv = *(const float4*)(bias + col);
            float4 v;
            v.x = acc[i][j + 0] + bv.x;
            v.y = acc[i][j + 1] + bv.y;
            v.z = acc[i][j + 2] + bv.z;
            v.w = acc[i][j + 3] + bv.w;
            if (EPI == 1) {
                v.x = gelu_exact(v.x);
                v.y = gelu_exact(v.y);
                v.z = gelu_exact(v.z);
                v.w = gelu_exact(v.w);
            }
            if (EPI == 2) {
                float4 rv = *(const float4*)(R + (size_t)row * N + col);
                v.x += rv.x; v.y += rv.y; v.z += rv.z; v.w += rv.w;
            }
            *(float4*)(C + (size_t)row * N + col) = v;
        }
    }
}

// ---------------------------------------------------------------------------
// Chunk scan: one block per (batch,chunk), 512 threads = one per feature d.
// Sequentially walks the 64 tokens of the chunk computing the phase cumsum,
// running means, and writes ctx = [cr | ci | rr | ri] (width 2048).
// ---------------------------------------------------------------------------
__global__ void __launch_bounds__(512)
chunk_kernel(const float* __restrict__ x, const float* __restrict__ omega,
             const float* __restrict__ log_scale, float* __restrict__ ctx)
{
    const int d = threadIdx.x;               // 0..511
    const size_t t0 = (size_t)blockIdx.x * CHUNK;
    const float scale_d = expf(log_scale[d]);

    float phi = 0.0f, sr = 0.0f, si = 0.0f;
#pragma unroll 4
    for (int c = 0; c < CHUNK; c++) {
        size_t t = t0 + c;
        float om = omega[t * DIM + d];
        phi += om * scale_d * rsqrtf((float)(c + 1));
        float sn, cs;
        sincosf(phi, &sn, &cs);
        float xv = x[t * DIM + d];
        float cr = xv * cs;
        float ci = xv * sn;
        sr += cr;
        si += ci;
        float inv = 1.0f / (float)(c + 1);
        float mr = sr * inv;
        float mi = si * inv;
        float rr = fmaf(mr, cs, mi * sn);
        float ri = fmaf(mi, cs, -mr * sn);
        float* o = ctx + t * CTXW;
        o[d]            = cr;
        o[DIM + d]      = ci;
        o[2 * DIM + d]  = rr;
        o[3 * DIM + d]  = ri;
    }
}

// ---------------------------------------------------------------------------
// LayerNorm over the 2048-wide ctx rows, in place. One block per token,
// 256 threads x 8 elements (two float4 each).
// ---------------------------------------------------------------------------
__global__ void __launch_bounds__(256)
ln_kernel(float* __restrict__ ctx, const float* __restrict__ gamma,
          const float* __restrict__ beta)
{
    const int row = blockIdx.x;
    const int tid = threadIdx.x;
    float* p = ctx + (size_t)row * CTXW;

    float4 a = *(const float4*)(p + tid * 4);
    float4 b = *(const float4*)(p + 1024 + tid * 4);

    float s = a.x + a.y + a.z + a.w + b.x + b.y + b.z + b.w;
    float q = a.x * a.x + a.y * a.y + a.z * a.z + a.w * a.w +
              b.x * b.x + b.y * b.y + b.z * b.z + b.w * b.w;

#pragma unroll
    for (int off = 16; off > 0; off >>= 1) {
        s += __shfl_xor_sync(0xFFFFFFFFu, s, off);
        q += __shfl_xor_sync(0xFFFFFFFFu, q, off);
    }
    __shared__ float ss[8], qq[8];
    const int w = tid >> 5, l = tid & 31;
    if (l == 0) { ss[w] = s; qq[w] = q; }
    __syncthreads();
    s = 0.0f; q = 0.0f;
#pragma unroll
    for (int i = 0; i < 8; i++) { s += ss[i]; q += qq[i]; }

    const float mu   = s * (1.0f / 2048.0f);
    const float var  = q * (1.0f / 2048.0f) - mu * mu;
    const float rstd = rsqrtf(var + LN_EPS);

    const int c0 = tid * 4;
    const int c1 = 1024 + tid * 4;
    float4 g0 = *(const float4*)(gamma + c0);
    float4 g1 = *(const float4*)(gamma + c1);
    float4 e0 = *(const float4*)(beta + c0);
    float4 e1 = *(const float4*)(beta + c1);

    a.x = (a.x - mu) * rstd * g0.x + e0.x;
    a.y = (a.y - mu) * rstd * g0.y + e0.y;
    a.z = (a.z - mu) * rstd * g0.z + e0.z;
    a.w = (a.w - mu) * rstd * g0.w + e0.w;
    b.x = (b.x - mu) * rstd * g1.x + e1.x;
    b.y = (b.y - mu) * rstd * g1.y + e1.y;
    b.z = (b.z - mu) * rstd * g1.z + e1.z;
    b.w = (b.w - mu) * rstd * g1.w + e1.w;

    *(float4*)(p + tid * 4)        = a;
    *(float4*)(p + 1024 + tid * 4) = b;
}

// ---------------------------------------------------------------------------
// Launch: 5 graph-capturable kernel launches, no sync, no allocation.
// Input order (metadata): x, W_omega, b_omega, log_scale, ln_gamma, ln_beta,
//                         W1, b1, W2, b2
// ---------------------------------------------------------------------------
extern "C" void kernel_launch(void* const* d_in, const int* in_sizes, int n_in,
                              void* d_out, int out_size)
{
    const float* x         = (const float*)d_in[0];
    const float* W_omega   = (const float*)d_in[1];
    const float* b_omega   = (const float*)d_in[2];
    const float* log_scale = (const float*)d_in[3];
    const float* ln_gamma  = (const float*)d_in[4];
    const float* ln_beta   = (const float*)d_in[5];
    const float* W1        = (const float*)d_in[6];
    const float* b1        = (const float*)d_in[7];
    const float* W2        = (const float*)d_in[8];
    const float* b2        = (const float*)d_in[9];
    float* out = (float*)d_out;

    void* p;
    cudaGetSymbolAddress(&p, g_omega); float* omega = (float*)p;
    cudaGetSymbolAddress(&p, g_ctx);   float* ctx   = (float*)p;
    cudaGetSymbolAddress(&p, g_h);     float* h     = (float*)p;

    // 1) omega = x @ W_omega + b_omega        [16384,512] = [16384,512]x[512,512]
    sgemm_kernel<0><<<dim3(DIM / BN, T_TOK / BM), 256>>>(
        x, W_omega, b_omega, nullptr, omega, T_TOK, DIM, DIM);

    // 2) chunk scan -> ctx [16384, 2048]
    chunk_kernel<<<NCHUNKS, 512>>>(x, omega, log_scale, ctx);

    // 3) LayerNorm(ctx) in place
    ln_kernel<<<T_TOK, 256>>>(ctx, ln_gamma, ln_beta);

    // 4) h = gelu(ctx @ W1 + b1)              [16384,1024] = [16384,2048]x[2048,1024]
    sgemm_kernel<1><<<dim3(HIDW / BN, T_TOK / BM), 256>>>(
        ctx, W1, b1, nullptr, h, T_TOK, HIDW, CTXW);

    // 5) out = x + (h @ W2 + b2)              [16384,512] = [16384,1024]x[1024,512]
    sgemm_kernel<2><<<dim3(DIM / BN, T_TOK / BM), 256>>>(
        h, W2, b2, x, out, T_TOK, DIM, HIDW);
}

// round 14
// speedup vs baseline: 1.0675x; 1.0675x over previous
#include <cuda_runtime.h>
#include <math.h>

// ---------------------------------------------------------------------------
// Problem constants: B=4, S=4096, D=512, CHUNK=64  ->  T = B*S = 16384 tokens
// ---------------------------------------------------------------------------
#define T_TOK   16384
#define DIM     512
#define CHUNK   64
#define NCHUNKS (T_TOK / CHUNK)      // 256
#define CTXW    (4 * DIM)            // 2048
#define HIDW    (2 * DIM)            // 1024
#define LN_EPS  1e-5f

// ---------------------------------------------------------------------------
// Scratch (allocation-free rule: __device__ globals)
// ---------------------------------------------------------------------------
__device__ float g_omega[(size_t)T_TOK * DIM];    //  33.5 MB
__device__ float g_ctx  [(size_t)T_TOK * CTXW];   // 134.2 MB (ctx, LN'd in place)
__device__ float g_h    [(size_t)T_TOK * HIDW];   //  67.1 MB (post-GELU hidden)

// ---------------------------------------------------------------------------
// SGEMM: C[M,N] = A[M,K] @ B[K,N] + bias, with epilogue variants.
// BM=BN=128, BK=16, 256 threads, 8x8 per-thread micro-tile.
// All M,N,K here are multiples of the tile sizes -> no bounds checks.
// EPI: 0 = bias only, 1 = bias + exact GELU (erf), 2 = bias + residual add
// ---------------------------------------------------------------------------
#define BM 128
#define BN 128
#define BK 16
#define TM 8
#define TN 8

__device__ __forceinline__ float gelu_exact(float v) {
    return 0.5f * v * (1.0f + erff(v * 0.70710678118654752440f));
}

template <int EPI>
__global__ void __launch_bounds__(256)
sgemm_kernel(const float* __restrict__ A, const float* __restrict__ B,
             const float* __restrict__ bias, const float* __restrict__ R,
             float* __restrict__ C, int M, int N, int K)
{
    __shared__ float As[BK][BM];   // A tile, transposed (k-major)
    __shared__ float Bs[BK][BN];

    const int tid = threadIdx.x;
    const int tx  = tid & 15;       // 0..15 -> col group
    const int ty  = tid >> 4;       // 0..15 -> row group
    const int rowBase = blockIdx.y * BM;
    const int colBase = blockIdx.x * BN;

    const float* Ab = A + (size_t)rowBase * K;
    const float* Bb = B + colBase;

    float acc[TM][TN];
#pragma unroll
    for (int i = 0; i < TM; i++)
#pragma unroll
        for (int j = 0; j < TN; j++) acc[i][j] = 0.0f;

    for (int k0 = 0; k0 < K; k0 += BK) {
        // ---- load A tile: 128 rows x 16 cols = 512 float4, 2 per thread ----
#pragma unroll
        for (int i = 0; i < 2; i++) {
            int id = i * 256 + tid;          // 0..511
            int r  = id >> 2;                // 0..127 (tile row)
            int kq = (id & 3) << 2;          // 0,4,8,12 (k offset)
            float4 v = *(const float4*)(Ab + (size_t)r * K + k0 + kq);
            As[kq + 0][r] = v.x;
            As[kq + 1][r] = v.y;
            As[kq + 2][r] = v.z;
            As[kq + 3][r] = v.w;
        }
        // ---- load B tile: 16 rows x 128 cols = 512 float4, 2 per thread ----
#pragma unroll
        for (int i = 0; i < 2; i++) {
            int id = i * 256 + tid;          // 0..511
            int kr = id >> 5;                // 0..15
            int cq = (id & 31) << 2;         // 0..124
            *(float4*)&Bs[kr][cq] =
                *(const float4*)(Bb + (size_t)(k0 + kr) * N + cq);
        }
        __syncthreads();

#pragma unroll
        for (int kk = 0; kk < BK; kk++) {
            float ra[TM], rb[TN];
#pragma unroll
            for (int i = 0; i < TM; i++) ra[i] = As[kk][ty * TM + i];
#pragma unroll
            for (int j = 0; j < TN; j++) rb[j] = Bs[kk][tx * TN + j];
#pragma unroll
            for (int i = 0; i < TM; i++)
#pragma unroll
                for (int j = 0; j < TN; j++)
                    acc[i][j] = fmaf(ra[i], rb[j], acc[i][j]);
        }
        __syncthreads();
    }

    // ---- epilogue ----
#pragma unroll
    for (int i = 0; i < TM; i++) {
        int row = rowBase + ty * TM + i;
#pragma unroll
        for (int j = 0; j < TN; j += 4) {
            int col = colBase + tx * TN + j;
            float4 bv = *(const float4*)(bias + col);
            float4 v;
            v.x = acc[i][j + 0] + bv.x;
            v.y = acc[i][j + 1] + bv.y;
            v.z = acc[i][j + 2] + bv.z;
            v.w = acc[i][j + 3] + bv.w;
            if (EPI == 1) {
                v.x = gelu_exact(v.x);
                v.y = gelu_exact(v.y);
                v.z = gelu_exact(v.z);
                v.w = gelu_exact(v.w);
            }
            if (EPI == 2) {
                float4 rv = *(const float4*)(R + (size_t)row * N + col);
                v.x += rv.x; v.y += rv.y; v.z += rv.z; v.w += rv.w;
            }
            *(float4*)(C + (size_t)row * N + col) = v;
        }
    }
}

// ---------------------------------------------------------------------------
// Chunk scan: one block per (batch,chunk), 512 threads = one per feature d.
// Sequentially walks the 64 tokens of the chunk computing the phase cumsum,
// running means, and writes ctx = [cr | ci | rr | ri] (width 2048).
// ---------------------------------------------------------------------------
__global__ void __launch_bounds__(512)
chunk_kernel(const float* __restrict__ x, const float* __restrict__ omega,
             const float* __restrict__ log_scale, float* __restrict__ ctx)
{
    const int d = threadIdx.x;               // 0..511
    const size_t t0 = (size_t)blockIdx.x * CHUNK;
    const float scale_d = expf(log_scale[d]);

    float phi = 0.0f, sr = 0.0f, si = 0.0f;
#pragma unroll 4
    for (int c = 0; c < CHUNK; c++) {
        size_t t = t0 + c;
        float om = omega[t * DIM + d];
        phi += om * scale_d * rsqrtf((float)(c + 1));
        float sn, cs;
        sincosf(phi, &sn, &cs);
        float xv = x[t * DIM + d];
        float cr = xv * cs;
        float ci = xv * sn;
        sr += cr;
        si += ci;
        float inv = 1.0f / (float)(c + 1);
        float mr = sr * inv;
        float mi = si * inv;
        float rr = fmaf(mr, cs, mi * sn);
        float ri = fmaf(mi, cs, -mr * sn);
        float* o = ctx + t * CTXW;
        o[d]            = cr;
        o[DIM + d]      = ci;
        o[2 * DIM + d]  = rr;
        o[3 * DIM + d]  = ri;
    }
}

// ---------------------------------------------------------------------------
// LayerNorm over the 2048-wide ctx rows, in place. One block per token,
// 256 threads x 8 elements (two float4 each).
// ---------------------------------------------------------------------------
__global__ void __launch_bounds__(256)
ln_kernel(float* __restrict__ ctx, const float* __restrict__ gamma,
          const float* __restrict__ beta)
{
    const int row = blockIdx.x;
    const int tid = threadIdx.x;
    float* p = ctx + (size_t)row * CTXW;

    float4 a = *(const float4*)(p + tid * 4);
    float4 b = *(const float4*)(p + 1024 + tid * 4);

    float s = a.x + a.y + a.z + a.w + b.x + b.y + b.z + b.w;
    float q = a.x * a.x + a.y * a.y + a.z * a.z + a.w * a.w +
              b.x * b.x + b.y * b.y + b.z * b.z + b.w * b.w;

#pragma unroll
    for (int off = 16; off > 0; off >>= 1) {
        s += __shfl_xor_sync(0xFFFFFFFFu, s, off);
        q += __shfl_xor_sync(0xFFFFFFFFu, q, off);
    }
    __shared__ float ss[8], qq[8];
    const int w = tid >> 5, l = tid & 31;
    if (l == 0) { ss[w] = s; qq[w] = q; }
    __syncthreads();
    s = 0.0f; q = 0.0f;
#pragma unroll
    for (int i = 0; i < 8; i++) { s += ss[i]; q += qq[i]; }

    const float mu   = s * (1.0f / 2048.0f);
    const float var  = q * (1.0f / 2048.0f) - mu * mu;
    const float rstd = rsqrtf(var + LN_EPS);

    const int c0 = tid * 4;
    const int c1 = 1024 + tid * 4;
    float4 g0 = *(const float4*)(gamma + c0);
    float4 g1 = *(const float4*)(gamma + c1);
    float4 e0 = *(const float4*)(beta + c0);
    float4 e1 = *(const float4*)(beta + c1);

    a.x = (a.x - mu) * rstd * g0.x + e0.x;
    a.y = (a.y - mu) * rstd * g0.y + e0.y;
    a.z = (a.z - mu) * rstd * g0.z + e0.z;
    a.w = (a.w - mu) * rstd * g0.w + e0.w;
    b.x = (b.x - mu) * rstd * g1.x + e1.x;
    b.y = (b.y - mu) * rstd * g1.y + e1.y;
    b.z = (b.z - mu) * rstd * g1.z + e1.z;
    b.w = (b.w - mu) * rstd * g1.w + e1.w;

    *(float4*)(p + tid * 4)        = a;
    *(float4*)(p + 1024 + tid * 4) = b;
}

// ---------------------------------------------------------------------------
// Launch: 5 graph-capturable kernel launches, no sync, no allocation.
// Input order (metadata): x, W_omega, b_omega, log_scale, ln_gamma, ln_beta,
//                         W1, b1, W2, b2
// ---------------------------------------------------------------------------
extern "C" void kernel_launch(void* const* d_in, const int* in_sizes, int n_in,
                              void* d_out, int out_size)
{
    const float* x         = (const float*)d_in[0];
    const float* W_omega   = (const float*)d_in[1];
    const float* b_omega   = (const float*)d_in[2];
    const float* log_scale = (const float*)d_in[3];
    const float* ln_gamma  = (const float*)d_in[4];
    const float* ln_beta   = (const float*)d_in[5];
    const float* W1        = (const float*)d_in[6];
    const float* b1        = (const float*)d_in[7];
    const float* W2        = (const float*)d_in[8];
    const float* b2        = (const float*)d_in[9];
    float* out = (float*)d_out;

    void* p;
    cudaGetSymbolAddress(&p, g_omega); float* omega = (float*)p;
    cudaGetSymbolAddress(&p, g_ctx);   float* ctx   = (float*)p;
    cudaGetSymbolAddress(&p, g_h);     float* h     = (float*)p;

    // 1) omega = x @ W_omega + b_omega        [16384,512] = [16384,512]x[512,512]
    sgemm_kernel<0><<<dim3(DIM / BN, T_TOK / BM), 256>>>(
        x, W_omega, b_omega, nullptr, omega, T_TOK, DIM, DIM);

    // 2) chunk scan -> ctx [16384, 2048]
    chunk_kernel<<<NCHUNKS, 512>>>(x, omega, log_scale, ctx);

    // 3) LayerNorm(ctx) in place
    ln_kernel<<<T_TOK, 256>>>(ctx, ln_gamma, ln_beta);

    // 4) h = gelu(ctx @ W1 + b1)              [16384,1024] = [16384,2048]x[2048,1024]
    sgemm_kernel<1><<<dim3(HIDW / BN, T_TOK / BM), 256>>>(
        ctx, W1, b1, nullptr, h, T_TOK, HIDW, CTXW);

    // 5) out = x + (h @ W2 + b2)              [16384,512] = [16384,1024]x[1024,512]
    sgemm_kernel<2><<<dim3(DIM / BN, T_TOK / BM), 256>>>(
        h, W2, b2, x, out, T_TOK, DIM, HIDW);
}